// round 2
// baseline (speedup 1.0000x reference)
#include <cuda_runtime.h>
#include <cuda_bf16.h>
#include <math.h>

// Problem constants
#define NN   50000
#define EE   800000
#define HID  128
#define SC   128
#define EIN  16
#define TT   5
#define NH   4
#define KK   4
#define INVAR 100
#define XDIM 484        // h_i(128) + h_j(128) + invar(100) + edge_feature(128)
#define XS   488        // padded row stride for x in shared (even!)
#define EPB  32         // edges per CTA
#define NPB  32         // nodes per CTA

// Accumulators (device globals: no allocation allowed)
__device__ float g_msg[(size_t)NN * HID];    // segment_sum(msg)
__device__ float g_zacc[(size_t)NN * 48];    // segment_sum(Z_agg)
__device__ float g_cnt[NN];                  // edge counts

// K-pair-packed weights: P[(k2*ncol + j)*2 + p] = W[(2*k2+p)*ncol + j]
__device__ __align__(16) float pWe [EIN  * HID];          // 16x128
__device__ __align__(16) float pWm1[XDIM * HID];          // 484x128
__device__ __align__(16) float pWm2[HID  * HID];          // 128x128
__device__ __align__(16) float pWv1[HID  * HID];          // 128x128
__device__ __align__(16) float pWv2[HID  * 80];           // 128x80
__device__ __align__(16) float pWs1[(SC+HID) * HID];      // 256x128
__device__ __align__(16) float pWs2[HID  * HID];          // 128x128

__device__ __forceinline__ float silu_f(float x) {
    return x / (1.0f + __expf(-x));
}

__device__ __forceinline__ void red4(float* p, float x, float y, float z, float w) {
    asm volatile("red.global.add.v4.f32 [%0], {%1,%2,%3,%4};"
                 :: "l"(p), "f"(x), "f"(y), "f"(z), "f"(w) : "memory");
}

// Packed fp32x2 FMA (SASS FFMA2): d = a*b + d elementwise on 2 packed floats
__device__ __forceinline__ void ffma2(unsigned long long& d,
                                      unsigned long long a,
                                      unsigned long long b) {
    asm("fma.rn.f32x2 %0, %1, %2, %0;" : "+l"(d) : "l"(a), "l"(b));
}

// horizontal sum of packed pair
__device__ __forceinline__ float psum(unsigned long long v) {
    return __uint_as_float((unsigned)v) + __uint_as_float((unsigned)(v >> 32));
}

// ---------------------------------------------------------------------------
// Packed-K GEMM tile: out[32][ncol] (+bias, opt silu) = A[32][Kdim] @ W
// 8 warps: warp -> 4 rows, lane -> 4 output cols (j0 = lane*4).
// A rows must be 8B aligned (sA even, base 8B aligned). P is k-pair packed.
// Safe to call under a lane predicate (no syncs inside).
// ---------------------------------------------------------------------------
__device__ __forceinline__ void gemm_p2(
    const float* A, int sA, int Kdim,
    const float* __restrict__ P, int ncol,
    const float* __restrict__ bias,
    float* outp, int sOut, int warp, int lane, bool act)
{
    unsigned long long acc[4][4];
    #pragma unroll
    for (int i = 0; i < 4; i++)
        #pragma unroll
        for (int j = 0; j < 4; j++) acc[i][j] = 0ULL;

    const unsigned long long* a0 = (const unsigned long long*)(A + (warp * 4 + 0) * sA);
    const unsigned long long* a1 = (const unsigned long long*)(A + (warp * 4 + 1) * sA);
    const unsigned long long* a2 = (const unsigned long long*)(A + (warp * 4 + 2) * sA);
    const unsigned long long* a3 = (const unsigned long long*)(A + (warp * 4 + 3) * sA);
    const int j0 = lane * 4;
    const int K2 = Kdim >> 1;

    #pragma unroll 2
    for (int k2 = 0; k2 < K2; k2++) {
        const ulonglong2* wp = (const ulonglong2*)(P + ((size_t)k2 * ncol + j0) * 2);
        ulonglong2 wa = __ldg(wp);       // cols j0, j0+1 (each ull = (w[2k2][j], w[2k2+1][j]))
        ulonglong2 wb = __ldg(wp + 1);   // cols j0+2, j0+3
        unsigned long long b0 = a0[k2], b1 = a1[k2], b2 = a2[k2], b3 = a3[k2];
        ffma2(acc[0][0], b0, wa.x); ffma2(acc[0][1], b0, wa.y);
        ffma2(acc[0][2], b0, wb.x); ffma2(acc[0][3], b0, wb.y);
        ffma2(acc[1][0], b1, wa.x); ffma2(acc[1][1], b1, wa.y);
        ffma2(acc[1][2], b1, wb.x); ffma2(acc[1][3], b1, wb.y);
        ffma2(acc[2][0], b2, wa.x); ffma2(acc[2][1], b2, wa.y);
        ffma2(acc[2][2], b2, wb.x); ffma2(acc[2][3], b2, wb.y);
        ffma2(acc[3][0], b3, wa.x); ffma2(acc[3][1], b3, wa.y);
        ffma2(acc[3][2], b3, wb.x); ffma2(acc[3][3], b3, wb.y);
    }

    float4 bv = __ldg((const float4*)(bias + j0));
    #pragma unroll
    for (int ee = 0; ee < 4; ee++) {
        float o0 = psum(acc[ee][0]) + bv.x;
        float o1 = psum(acc[ee][1]) + bv.y;
        float o2 = psum(acc[ee][2]) + bv.z;
        float o3 = psum(acc[ee][3]) + bv.w;
        if (act) { o0 = silu_f(o0); o1 = silu_f(o1); o2 = silu_f(o2); o3 = silu_f(o3); }
        float* o = outp + (warp * 4 + ee) * sOut + j0;
        o[0] = o0; o[1] = o1; o[2] = o2; o[3] = o3;
    }
}

// ---------------------------------------------------------------------------
// Zero accumulators + repack weights into k-pair-packed layouts
// ---------------------------------------------------------------------------
__device__ __forceinline__ void repack_one(const float* __restrict__ W, float* __restrict__ P,
                                           int Kdim, int ncol, size_t idx, size_t stride) {
    size_t tot = (size_t)Kdim * ncol;
    for (size_t i = idx; i < tot; i += stride) {
        // i indexes dst: i = (k2*ncol + j)*2 + p
        size_t p  = i & 1;
        size_t kj = i >> 1;
        size_t k2 = kj / ncol;
        size_t j  = kj % ncol;
        P[i] = W[(2 * k2 + p) * ncol + j];
    }
}

__global__ void prep_kernel(const float* __restrict__ We,  const float* __restrict__ Wm1,
                            const float* __restrict__ Wm2, const float* __restrict__ Wv1,
                            const float* __restrict__ Wv2, const float* __restrict__ Ws1,
                            const float* __restrict__ Ws2) {
    size_t idx = (size_t)blockIdx.x * blockDim.x + threadIdx.x;
    size_t stride = (size_t)gridDim.x * blockDim.x;
    for (size_t i = idx; i < (size_t)NN * HID; i += stride) g_msg[i] = 0.0f;
    for (size_t i = idx; i < (size_t)NN * 48; i += stride) g_zacc[i] = 0.0f;
    for (size_t i = idx; i < NN; i += stride) g_cnt[i] = 0.0f;
    repack_one(We,  pWe,  EIN,      HID, idx, stride);
    repack_one(Wm1, pWm1, XDIM,     HID, idx, stride);
    repack_one(Wm2, pWm2, HID,      HID, idx, stride);
    repack_one(Wv1, pWv1, HID,      HID, idx, stride);
    repack_one(Wv2, pWv2, HID,      80,  idx, stride);
    repack_one(Ws1, pWs1, SC + HID, HID, idx, stride);
    repack_one(Ws2, pWs2, HID,      HID, idx, stride);
}

// ---------------------------------------------------------------------------
// Edge kernel: 32 edges per 256-thread CTA
// ---------------------------------------------------------------------------
__global__ void __launch_bounds__(256, 2) edge_kernel(
    const float* __restrict__ Z, const float* __restrict__ h,
    const int* __restrict__ ei,
    const float* __restrict__ edf, const float* __restrict__ edv,
    const float* __restrict__ be,  const float* __restrict__ bm1,
    const float* __restrict__ bm2, const float* __restrict__ bv1,
    const float* __restrict__ bv2)
{
    extern __shared__ float sm[];
    float* xs   = sm;               // 32 * 488 = 15616  (x, later basis in cols 0..79)
    float* zs   = sm + 15616;       // 32 * 64  = 2048   (Z_ij, layout d*20+t*4+h)
    float* h1   = sm + 17664;       // 32 * 128 = 4096
    float* h2   = sm + 21760;       // 32 * 128 = 4096   (msg)
    float* edfs = sm + 25856;       // 512
    int*   ssrc = (int*)(sm + 26368); // 32
    int*   sdst = ssrc + 32;          // 32

    const int tid  = threadIdx.x;
    const int warp = tid >> 5;
    const int lane = tid & 31;
    const int e0   = blockIdx.x * EPB;

    // ---- Phase 0: stage inputs ----
    if (tid < EPB) {
        ssrc[tid] = ei[e0 + tid];
        sdst[tid] = ei[EE + e0 + tid];
    }
    for (int i = tid; i < EPB * EIN; i += 256) edfs[i] = edf[(size_t)e0 * EIN + i];
    __syncthreads();

    // gather h: x[0:128] = h[dst] (h_i), x[128:256] = h[src] (h_j)
    for (int i = tid; i < EPB * 32; i += 256) {
        int e = i >> 5, c = i & 31;
        float4 vi = __ldg((const float4*)(h + (size_t)sdst[e] * 128 + c * 4));
        float4 vj = __ldg((const float4*)(h + (size_t)ssrc[e] * 128 + c * 4));
        *(float4*)(xs + e * XS + c * 4) = vi;
        *(float4*)(xs + e * XS + 128 + c * 4) = vj;
    }
    // Z_ij, t < 4: Z[dst] - Z[src]
    for (int i = tid; i < EPB * 48; i += 256) {
        int e = i / 48, r = i % 48;
        int d = r >> 4, q = r & 15;
        float v = __ldg(Z + (size_t)sdst[e] * 48 + r) - __ldg(Z + (size_t)ssrc[e] * 48 + r);
        zs[e * 64 + d * 20 + q] = v;
    }
    // Z_ij, t == 4: edge_distance_vec broadcast over heads
    for (int i = tid; i < EPB * 12; i += 256) {
        int e = i / 12, r = i % 12;
        int d = r >> 2, hh = r & 3;
        zs[e * 64 + d * 20 + 16 + hh] = __ldg(edv + (size_t)(e0 + e) * 3 + d);
    }
    __syncthreads();

    // ---- invariants + L2 normalize (one warp per 4 edges) ----
    for (int eloc = 0; eloc < 4; eloc++) {
        int e = warp * 4 + eloc;
        float v[4];
        float sq = 0.0f;
        #pragma unroll
        for (int u = 0; u < 4; u++) {
            int m = lane + u * 32;
            float val = 0.0f;
            if (m < INVAR) {
                int t = m / 20, rem = m % 20;
                int r2 = rem >> 2, hh = rem & 3;
                const float* z = zs + e * 64;
                val = z[0 * 20 + t * 4 + hh] * z[0 * 20 + r2 * 4 + hh]
                    + z[1 * 20 + t * 4 + hh] * z[1 * 20 + r2 * 4 + hh]
                    + z[2 * 20 + t * 4 + hh] * z[2 * 20 + r2 * 4 + hh];
            }
            v[u] = val;
            sq += val * val;
        }
        #pragma unroll
        for (int off = 16; off > 0; off >>= 1)
            sq += __shfl_xor_sync(0xffffffffu, sq, off);
        float inv = 1.0f / fmaxf(sqrtf(sq), 1e-12f);
        #pragma unroll
        for (int u = 0; u < 4; u++) {
            int m = lane + u * 32;
            if (m < INVAR) xs[e * XS + 256 + m] = v[u] * inv;
        }
    }
    __syncthreads();

    // ---- edge_feature = edf @ We + be -> x[356:484] ----
    gemm_p2(edfs, EIN, EIN, pWe, HID, be, xs + 356, XS, warp, lane, false);
    __syncthreads();

    // ---- msg MLP + vec MLP (packed-K FFMA2 GEMMs) ----
    gemm_p2(xs, XS, XDIM, pWm1, HID, bm1, h1, 128, warp, lane, true);   // hid1
    __syncthreads();
    gemm_p2(h1, 128, 128, pWm2, HID, bm2, h2, 128, warp, lane, true);   // msg
    __syncthreads();
    gemm_p2(h2, 128, 128, pWv1, HID, bv1, h1, 128, warp, lane, true);   // vh
    __syncthreads();

    // basis = vh @ Wv2 + bv2  (ncol = 80), store into xs[e][0..79]
    if (lane < 20)
        gemm_p2(h1, 128, 128, pWv2, 80, bv2, xs, XS, warp, lane, false);
    __syncthreads();

    // ---- Phase 5: scatter-reduce ----
    // msg sum
    for (int i = tid; i < EPB * 32; i += 256) {
        int e = i >> 5, c = i & 31;
        const float4 v = *(const float4*)(h2 + e * 128 + c * 4);
        red4(g_msg + (size_t)sdst[e] * 128 + c * 4, v.x, v.y, v.z, v.w);
    }
    // counts
    if (tid < EPB) atomicAdd(&g_cnt[sdst[tid]], 1.0f);
    // Z_agg[e][d][k][h] = sum_t Zij[d][t][h] * basis[t][k][h]
    for (int i = tid; i < EPB * 12; i += 256) {
        int e = i / 12, rr = i % 12;
        int d = rr >> 2, kk = rr & 3;
        const float* z  = zs + e * 64 + d * 20;     // z[t*4 + h]
        const float* bs = xs + e * XS + kk * 4;     // bs[t*16 + h]
        float o[4];
        #pragma unroll
        for (int hh = 0; hh < 4; hh++) {
            float s = 0.0f;
            #pragma unroll
            for (int t = 0; t < TT; t++)
                s += z[t * 4 + hh] * bs[t * 16 + hh];
            o[hh] = s;
        }
        red4(g_zacc + (size_t)sdst[e] * 48 + rr * 4, o[0], o[1], o[2], o[3]);
    }
}

// ---------------------------------------------------------------------------
// Node kernel: 32 nodes per 256-thread CTA
// out layout: [ Z_out : NN*48 floats ][ h_out : NN*128 floats ]
// ---------------------------------------------------------------------------
__global__ void __launch_bounds__(256, 2) node_kernel(
    const float* __restrict__ h,
    const float* __restrict__ bs1, const float* __restrict__ bs2,
    float* __restrict__ out)
{
    extern __shared__ float sm[];
    float* xn = sm;            // 32 * 256
    float* t1 = sm + 8192;     // 32 * 128
    float* t2 = sm + 12288;    // 32 * 128

    const int tid  = threadIdx.x;
    const int warp = tid >> 5;
    const int lane = tid & 31;
    const int n0   = blockIdx.x * NPB;

    // load x = concat(h[n], msg_sum[n])
    for (int i = tid; i < NPB * 64; i += 256) {
        int v = i >> 6, c = i & 63;
        int n = n0 + v;
        int nc = n < NN ? n : (NN - 1);
        float4 val;
        if (c < 32) val = __ldg((const float4*)(h + (size_t)nc * 128 + c * 4));
        else        val = *(const float4*)(g_msg + (size_t)nc * 128 + (c - 32) * 4);
        *(float4*)(xn + v * 256 + c * 4) = val;
    }
    __syncthreads();

    gemm_p2(xn, 256, 256, pWs1, HID, bs1, t1, 128, warp, lane, true);
    __syncthreads();
    gemm_p2(t1, 128, 128, pWs2, HID, bs2, t2, 128, warp, lane, false);
    __syncthreads();

    // write h_out
    for (int i = tid; i < NPB * 32; i += 256) {
        int v = i >> 5, c = i & 31;
        int n = n0 + v;
        if (n < NN)
            *(float4*)(out + (size_t)NN * 48 + (size_t)n * 128 + c * 4) =
                *(const float4*)(t2 + v * 128 + c * 4);
    }

    // Z_out = Z_acc / max(cnt, 1)
    for (int i = tid; i < NPB * 48; i += 256) {
        int v = i / 48, r = i % 48;
        int n = n0 + v;
        if (n < NN) {
            float c = fmaxf(g_cnt[n], 1.0f);
            out[(size_t)n * 48 + r] = g_zacc[(size_t)n * 48 + r] * (1.0f / c);
        }
    }
}

// ---------------------------------------------------------------------------
extern "C" void kernel_launch(void* const* d_in, const int* in_sizes, int n_in,
                              void* d_out, int out_size) {
    const float* Z   = (const float*)d_in[0];
    const float* h   = (const float*)d_in[1];
    const int*   ei  = (const int*)d_in[2];
    const float* edf = (const float*)d_in[3];
    const float* edv = (const float*)d_in[4];
    // d_in[5] = edge_distance (unused by the reference)
    const float* We  = (const float*)d_in[6];
    const float* be  = (const float*)d_in[7];
    const float* Wm1 = (const float*)d_in[8];
    const float* bm1 = (const float*)d_in[9];
    const float* Wm2 = (const float*)d_in[10];
    const float* bm2 = (const float*)d_in[11];
    const float* Wv1 = (const float*)d_in[12];
    const float* bv1 = (const float*)d_in[13];
    const float* Wv2 = (const float*)d_in[14];
    const float* bv2 = (const float*)d_in[15];
    const float* Ws1 = (const float*)d_in[16];
    const float* bs1 = (const float*)d_in[17];
    const float* Ws2 = (const float*)d_in[18];
    const float* bs2 = (const float*)d_in[19];
    float* out = (float*)d_out;

    const int edge_smem = 26432 * 4;   // 105,728 B
    const int node_smem = 16384 * 4;   // 65,536 B
    cudaFuncSetAttribute(edge_kernel, cudaFuncAttributeMaxDynamicSharedMemorySize, edge_smem);
    cudaFuncSetAttribute(node_kernel, cudaFuncAttributeMaxDynamicSharedMemorySize, node_smem);

    prep_kernel<<<1024, 256>>>(We, Wm1, Wm2, Wv1, Wv2, Ws1, Ws2);
    edge_kernel<<<EE / EPB, 256, edge_smem>>>(Z, h, ei, edf, edv,
                                              be, bm1, bm2, bv1, bv2);
    node_kernel<<<(NN + NPB - 1) / NPB, 256, node_smem>>>(h, bs1, bs2, out);
}

// round 6
// speedup vs baseline: 1.2363x; 1.2363x over previous
#include <cuda_runtime.h>
#include <cuda_bf16.h>
#include <math.h>

// Problem constants
#define NN   50000
#define EE   800000
#define HID  128
#define SC   128
#define EIN  16
#define TT   5
#define NH   4
#define KK   4
#define INVAR 100
#define XDIM 484        // h_i(128) + h_j(128) + invar(100) + edge_feature(128)
#define EPB  32         // edges per CTA
#define NPB  32         // nodes per CTA
#define AS   66         // packed-activation k2-stride in floats (32 rows * 2 + 2 pad)

// Accumulators (device globals: no allocation allowed)
__device__ float g_msg[(size_t)NN * HID];    // segment_sum(msg)
__device__ float g_zacc[(size_t)NN * 48];    // segment_sum(Z_agg)
__device__ float g_cnt[NN];                  // edge counts

// K-pair-packed weights: P[(k2*ncol + j)*2 + p] = W[(2*k2+p)*ncol + j]
__device__ __align__(16) float pWe [EIN  * HID];          // 16x128
__device__ __align__(16) float pWm1[XDIM * HID];          // 484x128
__device__ __align__(16) float pWm2[HID  * HID];          // 128x128
__device__ __align__(16) float pWv1[HID  * HID];          // 128x128
__device__ __align__(16) float pWv2[HID  * 80];           // 128x80
__device__ __align__(16) float pWs1[(SC+HID) * HID];      // 256x128
__device__ __align__(16) float pWs2[HID  * HID];          // 128x128

__device__ __forceinline__ float silu_f(float x) {
    return x / (1.0f + __expf(-x));
}

__device__ __forceinline__ void red4(float* p, float x, float y, float z, float w) {
    asm volatile("red.global.add.v4.f32 [%0], {%1,%2,%3,%4};"
                 :: "l"(p), "f"(x), "f"(y), "f"(z), "f"(w) : "memory");
}

// Packed fp32x2 FMA (SASS FFMA2): d = a*b + d elementwise on 2 packed floats
__device__ __forceinline__ void ffma2(unsigned long long& d,
                                      unsigned long long a,
                                      unsigned long long b) {
    asm("fma.rn.f32x2 %0, %1, %2, %0;" : "+l"(d) : "l"(a), "l"(b));
}

__device__ __forceinline__ float psum(unsigned long long v) {
    return __uint_as_float((unsigned)v) + __uint_as_float((unsigned)(v >> 32));
}

// ---------------------------------------------------------------------------
// Column-sliced packed-K GEMM: out[32 rows][ncol] = act(A @ W + b)
// A is k-major packed in shared: Ap[k2*AS + row*2 + p] = A[row][2*k2+p].
// Warp w owns cols [16w, 16w+16). lane -> r4 = lane>>2 (rows r4+8i), c = lane&3
// (cols j0 = 16w + 4c .. +3). Weight loads are NON-redundant across warps.
// If TOG: write float4 row-major to outG (row = rowbase + r, stride 128,
// guarded by rowmax). Else: write packed into outSp (stride AS).
// Safe to call under a warp predicate (no syncs inside).
// ---------------------------------------------------------------------------
template<bool ACT, bool TOG>
__device__ __forceinline__ void gemm_pk(
    const float* Ap, int K2,
    const float* __restrict__ P, int ncol,
    const float* __restrict__ bias,
    float* outSp, float* outG, int rowbase, int rowmax,
    int warp, int lane)
{
    const int r4 = lane >> 2;
    const int c  = lane & 3;
    const int j0 = warp * 16 + c * 4;

    unsigned long long acc[4][4];
    #pragma unroll
    for (int i = 0; i < 4; i++)
        #pragma unroll
        for (int j = 0; j < 4; j++) acc[i][j] = 0ULL;

    #pragma unroll 2
    for (int k2 = 0; k2 < K2; k2++) {
        const float* pp = P + ((size_t)k2 * ncol + j0) * 2;
        ulonglong2 wa = __ldg((const ulonglong2*)pp);        // cols j0, j0+1
        ulonglong2 wb = __ldg((const ulonglong2*)(pp + 4));  // cols j0+2, j0+3
        const float* ab = Ap + k2 * AS + r4 * 2;
        unsigned long long a0 = *(const unsigned long long*)(ab);       // row r4
        unsigned long long a1 = *(const unsigned long long*)(ab + 16);  // row r4+8
        unsigned long long a2 = *(const unsigned long long*)(ab + 32);  // row r4+16
        unsigned long long a3 = *(const unsigned long long*)(ab + 48);  // row r4+24
        ffma2(acc[0][0], a0, wa.x); ffma2(acc[0][1], a0, wa.y);
        ffma2(acc[0][2], a0, wb.x); ffma2(acc[0][3], a0, wb.y);
        ffma2(acc[1][0], a1, wa.x); ffma2(acc[1][1], a1, wa.y);
        ffma2(acc[1][2], a1, wb.x); ffma2(acc[1][3], a1, wb.y);
        ffma2(acc[2][0], a2, wa.x); ffma2(acc[2][1], a2, wa.y);
        ffma2(acc[2][2], a2, wb.x); ffma2(acc[2][3], a2, wb.y);
        ffma2(acc[3][0], a3, wa.x); ffma2(acc[3][1], a3, wa.y);
        ffma2(acc[3][2], a3, wb.x); ffma2(acc[3][3], a3, wb.y);
    }

    float4 bv = __ldg((const float4*)(bias + j0));
    #pragma unroll
    for (int i = 0; i < 4; i++) {
        int r = r4 + 8 * i;
        float o0 = psum(acc[i][0]) + bv.x;
        float o1 = psum(acc[i][1]) + bv.y;
        float o2 = psum(acc[i][2]) + bv.z;
        float o3 = psum(acc[i][3]) + bv.w;
        if (ACT) { o0 = silu_f(o0); o1 = silu_f(o1); o2 = silu_f(o2); o3 = silu_f(o3); }
        if (TOG) {
            int row = rowbase + r;
            if (row < rowmax) {
                float4 v; v.x = o0; v.y = o1; v.z = o2; v.w = o3;
                *(float4*)(outG + (size_t)row * 128 + j0) = v;
            }
        } else {
            int c2 = j0 >> 1;
            float2 pa; pa.x = o0; pa.y = o1;
            float2 pb; pb.x = o2; pb.y = o3;
            *(float2*)(outSp + (c2 + 0) * AS + r * 2) = pa;
            *(float2*)(outSp + (c2 + 1) * AS + r * 2) = pb;
        }
    }
}

// ---------------------------------------------------------------------------
// Zero accumulators + repack weights into k-pair-packed layouts
// ---------------------------------------------------------------------------
__device__ __forceinline__ void repack_one(const float* __restrict__ W, float* __restrict__ P,
                                           int Kdim, int ncol, size_t idx, size_t stride) {
    size_t tot = (size_t)Kdim * ncol;
    for (size_t i = idx; i < tot; i += stride) {
        size_t p  = i & 1;
        size_t kj = i >> 1;
        size_t k2 = kj / ncol;
        size_t j  = kj % ncol;
        P[i] = W[(2 * k2 + p) * ncol + j];
    }
}

__global__ void prep_kernel(const float* __restrict__ We,  const float* __restrict__ Wm1,
                            const float* __restrict__ Wm2, const float* __restrict__ Wv1,
                            const float* __restrict__ Wv2, const float* __restrict__ Ws1,
                            const float* __restrict__ Ws2) {
    size_t idx = (size_t)blockIdx.x * blockDim.x + threadIdx.x;
    size_t stride = (size_t)gridDim.x * blockDim.x;
    for (size_t i = idx; i < (size_t)NN * HID; i += stride) g_msg[i] = 0.0f;
    for (size_t i = idx; i < (size_t)NN * 48; i += stride) g_zacc[i] = 0.0f;
    for (size_t i = idx; i < NN; i += stride) g_cnt[i] = 0.0f;
    repack_one(We,  pWe,  EIN,      HID, idx, stride);
    repack_one(Wm1, pWm1, XDIM,     HID, idx, stride);
    repack_one(Wm2, pWm2, HID,      HID, idx, stride);
    repack_one(Wv1, pWv1, HID,      HID, idx, stride);
    repack_one(Wv2, pWv2, HID,      80,  idx, stride);
    repack_one(Ws1, pWs1, SC + HID, HID, idx, stride);
    repack_one(Ws2, pWs2, HID,      HID, idx, stride);
}

// ncu alignment shims (so -s 5 lands on edge_kernel)
__global__ void dummy_kernel() {}

// ---------------------------------------------------------------------------
// Edge kernel: 32 edges per 256-thread CTA
// Packed shared buffers (stride AS per k2 pair):
//   xp:   242 k2  (x: h_i 0..63, h_j 64..127, invar 128..177.5, ef 178..241)
//   h1p/h2p: 64 k2
// ---------------------------------------------------------------------------
__global__ void __launch_bounds__(256, 2) edge_kernel(
    const float* __restrict__ Z, const float* __restrict__ h,
    const int* __restrict__ ei,
    const float* __restrict__ edf, const float* __restrict__ edv,
    const float* __restrict__ be,  const float* __restrict__ bm1,
    const float* __restrict__ bm2, const float* __restrict__ bv1,
    const float* __restrict__ bv2)
{
    extern __shared__ float sm[];
    float* xp   = sm;                    // 242*AS = 15972
    float* zs   = xp + 242 * AS;         // 32*64 = 2048  (Z_ij, d*20+t*4+h)
    float* h1p  = zs + 2048;             // 64*AS = 4224
    float* h2p  = h1p + 64 * AS;         // 64*AS = 4224
    float* edfp = h2p + 64 * AS;         // 8*AS = 528
    int*   ssrc = (int*)(edfp + 8 * AS); // 32
    int*   sdst = ssrc + 32;             // 32

    const int tid  = threadIdx.x;
    const int warp = tid >> 5;
    const int lane = tid & 31;
    const int e0   = blockIdx.x * EPB;

    // ---- Phase 0: stage indices + edf (packed) ----
    if (tid < EPB) {
        ssrc[tid] = ei[e0 + tid];
        sdst[tid] = ei[EE + e0 + tid];
    }
    for (int i = tid; i < EPB * EIN; i += 256) {
        int e = i >> 4, k = i & 15;
        edfp[(k >> 1) * AS + e * 2 + (k & 1)] = edf[(size_t)(e0 + e) * EIN + k];
    }
    __syncthreads();

    // ---- gather h into packed xp: k2 [0,64) = h[dst], [64,128) = h[src] ----
    for (int i = tid; i < EPB * 32; i += 256) {
        int e = i & 31, c = i >> 5;   // per warp: fixed e? no: e varies per lane? e = i&31 -> lanes distinct e
        // NOTE: e = i & 31 gives uncoalesced global gathers; use e = i >> 5 form:
        (void)e; (void)c;
        break;
    }
    // coalesced gather: warp handles one edge, lanes = 32 column-groups of 4
    for (int i = tid; i < EPB * 32; i += 256) {
        int e = i >> 5, c = i & 31;
        float4 vi = __ldg((const float4*)(h + (size_t)sdst[e] * 128 + c * 4));
        float4 vj = __ldg((const float4*)(h + (size_t)ssrc[e] * 128 + c * 4));
        float2 a, b;
        a.x = vi.x; a.y = vi.y; b.x = vi.z; b.y = vi.w;
        *(float2*)(xp + (2 * c + 0) * AS + e * 2) = a;
        *(float2*)(xp + (2 * c + 1) * AS + e * 2) = b;
        a.x = vj.x; a.y = vj.y; b.x = vj.z; b.y = vj.w;
        *(float2*)(xp + (64 + 2 * c + 0) * AS + e * 2) = a;
        *(float2*)(xp + (64 + 2 * c + 1) * AS + e * 2) = b;
    }
    // Z_ij, t < 4: Z[dst] - Z[src]
    for (int i = tid; i < EPB * 48; i += 256) {
        int e = i / 48, r = i % 48;
        int d = r >> 4, q = r & 15;
        float v = __ldg(Z + (size_t)sdst[e] * 48 + r) - __ldg(Z + (size_t)ssrc[e] * 48 + r);
        zs[e * 64 + d * 20 + q] = v;
    }
    // Z_ij, t == 4: edge_distance_vec broadcast over heads
    for (int i = tid; i < EPB * 12; i += 256) {
        int e = i / 12, r = i % 12;
        int d = r >> 2, hh = r & 3;
        zs[e * 64 + d * 20 + 16 + hh] = __ldg(edv + (size_t)(e0 + e) * 3 + d);
    }
    __syncthreads();

    // ---- invariants + L2 normalize (one warp per 4 edges) -> x[256..355] ----
    for (int eloc = 0; eloc < 4; eloc++) {
        int e = warp * 4 + eloc;
        float v[4];
        float sq = 0.0f;
        #pragma unroll
        for (int u = 0; u < 4; u++) {
            int m = lane + u * 32;
            float val = 0.0f;
            if (m < INVAR) {
                int t = m / 20, rem = m % 20;
                int r2 = rem >> 2, hh = rem & 3;
                const float* z = zs + e * 64;
                val = z[0 * 20 + t * 4 + hh] * z[0 * 20 + r2 * 4 + hh]
                    + z[1 * 20 + t * 4 + hh] * z[1 * 20 + r2 * 4 + hh]
                    + z[2 * 20 + t * 4 + hh] * z[2 * 20 + r2 * 4 + hh];
            }
            v[u] = val;
            sq += val * val;
        }
        #pragma unroll
        for (int off = 16; off > 0; off >>= 1)
            sq += __shfl_xor_sync(0xffffffffu, sq, off);
        float inv = 1.0f / fmaxf(sqrtf(sq), 1e-12f);
        #pragma unroll
        for (int u = 0; u < 4; u++) {
            int m = lane + u * 32;
            if (m < INVAR) {
                int k = 256 + m;
                xp[(k >> 1) * AS + e * 2 + (k & 1)] = v[u] * inv;
            }
        }
    }

    // ---- edge_feature = edf @ We + be -> x[356..483] (k2 178..241) ----
    gemm_pk<false, false>(edfp, EIN / 2, pWe, HID, be,
                          xp + 178 * AS, nullptr, 0, 0, warp, lane);
    __syncthreads();

    // ---- msg MLP + vec MLP ----
    gemm_pk<true, false>(xp,  XDIM / 2, pWm1, HID, bm1, h1p, nullptr, 0, 0, warp, lane);
    __syncthreads();
    gemm_pk<true, false>(h1p, HID / 2,  pWm2, HID, bm2, h2p, nullptr, 0, 0, warp, lane);
    __syncthreads();
    gemm_pk<true, false>(h2p, HID / 2,  pWv1, HID, bv1, h1p, nullptr, 0, 0, warp, lane);
    __syncthreads();

    // basis = vh @ Wv2 + bv2 (ncol=80): warps 0..4 cover 80 cols; write into xp[0..39]
    if (warp < 5)
        gemm_pk<false, false>(h1p, HID / 2, pWv2, 80, bv2, xp, nullptr, 0, 0, warp, lane);
    __syncthreads();

    // ---- scatter-reduce ----
    // msg sum (h2p packed -> float4 red)
    for (int i = tid; i < EPB * 32; i += 256) {
        int e = i >> 5, c = i & 31;
        float2 a = *(const float2*)(h2p + (2 * c + 0) * AS + e * 2);
        float2 b = *(const float2*)(h2p + (2 * c + 1) * AS + e * 2);
        red4(g_msg + (size_t)sdst[e] * 128 + c * 4, a.x, a.y, b.x, b.y);
    }
    // counts
    if (tid < EPB) atomicAdd(&g_cnt[sdst[tid]], 1.0f);
    // Z_agg[e][d][k][h] = sum_t Zij[d][t][h] * basis[t][k][h]
    for (int i = tid; i < EPB * 12; i += 256) {
        int e = i / 12, rr = i % 12;
        int d = rr >> 2, kk = rr & 3;
        const float* z = zs + e * 64 + d * 20;   // z[t*4 + h]
        float o[4];
        #pragma unroll
        for (int hh = 0; hh < 4; hh++) {
            float s = 0.0f;
            #pragma unroll
            for (int t = 0; t < TT; t++) {
                int k = t * 16 + kk * 4 + hh;    // basis index
                s += z[t * 4 + hh] * xp[(k >> 1) * AS + e * 2 + (k & 1)];
            }
            o[hh] = s;
        }
        red4(g_zacc + (size_t)sdst[e] * 48 + rr * 4, o[0], o[1], o[2], o[3]);
    }
}

// ---------------------------------------------------------------------------
// Node kernel: 32 nodes per 256-thread CTA
// out layout: [ Z_out : NN*48 floats ][ h_out : NN*128 floats ]
// ---------------------------------------------------------------------------
__global__ void __launch_bounds__(256, 2) node_kernel(
    const float* __restrict__ h,
    const float* __restrict__ bs1, const float* __restrict__ bs2,
    float* __restrict__ out)
{
    extern __shared__ float sm[];
    float* xnp = sm;                 // 128*AS = 8448
    float* t1p = sm + 128 * AS;      // 64*AS = 4224

    const int tid  = threadIdx.x;
    const int warp = tid >> 5;
    const int lane = tid & 31;
    const int n0   = blockIdx.x * NPB;

    // load x = concat(h[n], msg_sum[n]) into packed xnp
    for (int i = tid; i < NPB * 64; i += 256) {
        int v = i >> 6, c = i & 63;
        int n = n0 + v;
        int nc = n < NN ? n : (NN - 1);
        float4 val;
        if (c < 32) val = __ldg((const float4*)(h + (size_t)nc * 128 + c * 4));
        else        val = *(const float4*)(g_msg + (size_t)nc * 128 + (c - 32) * 4);
        float2 a, b;
        a.x = val.x; a.y = val.y; b.x = val.z; b.y = val.w;
        *(float2*)(xnp + (2 * c + 0) * AS + v * 2) = a;
        *(float2*)(xnp + (2 * c + 1) * AS + v * 2) = b;
    }
    __syncthreads();

    gemm_pk<true, false>(xnp, (SC + HID) / 2, pWs1, HID, bs1, t1p, nullptr, 0, 0, warp, lane);
    __syncthreads();
    // final layer -> global h_out directly
    gemm_pk<false, true>(t1p, HID / 2, pWs2, HID, bs2,
                         nullptr, out + (size_t)NN * 48, n0, NN, warp, lane);

    // Z_out = Z_acc / max(cnt, 1)
    for (int i = tid; i < NPB * 48; i += 256) {
        int v = i / 48, r = i % 48;
        int n = n0 + v;
        if (n < NN) {
            float c = fmaxf(g_cnt[n], 1.0f);
            out[(size_t)n * 48 + r] = g_zacc[(size_t)n * 48 + r] * (1.0f / c);
        }
    }
}

// ---------------------------------------------------------------------------
extern "C" void kernel_launch(void* const* d_in, const int* in_sizes, int n_in,
                              void* d_out, int out_size) {
    const float* Z   = (const float*)d_in[0];
    const float* h   = (const float*)d_in[1];
    const int*   ei  = (const int*)d_in[2];
    const float* edf = (const float*)d_in[3];
    const float* edv = (const float*)d_in[4];
    // d_in[5] = edge_distance (unused by the reference)
    const float* We  = (const float*)d_in[6];
    const float* be  = (const float*)d_in[7];
    const float* Wm1 = (const float*)d_in[8];
    const float* bm1 = (const float*)d_in[9];
    const float* Wm2 = (const float*)d_in[10];
    const float* bm2 = (const float*)d_in[11];
    const float* Wv1 = (const float*)d_in[12];
    const float* bv1 = (const float*)d_in[13];
    const float* Wv2 = (const float*)d_in[14];
    const float* bv2 = (const float*)d_in[15];
    const float* Ws1 = (const float*)d_in[16];
    const float* bs1 = (const float*)d_in[17];
    const float* Ws2 = (const float*)d_in[18];
    const float* bs2 = (const float*)d_in[19];
    float* out = (float*)d_out;

    // edge smem: 242*66 + 2048 + 64*66*2 + 8*66 + 64 ints
    const int edge_floats = 242 * AS + 2048 + 64 * AS + 64 * AS + 8 * AS + 64;
    const int edge_smem = edge_floats * 4;
    const int node_smem = (128 * AS + 64 * AS) * 4;
    cudaFuncSetAttribute(edge_kernel, cudaFuncAttributeMaxDynamicSharedMemorySize, edge_smem);
    cudaFuncSetAttribute(node_kernel, cudaFuncAttributeMaxDynamicSharedMemorySize, node_smem);

    prep_kernel<<<1024, 256>>>(We, Wm1, Wm2, Wv1, Wv2, Ws1, Ws2);
    dummy_kernel<<<1, 32>>>();
    dummy_kernel<<<1, 32>>>();
    edge_kernel<<<EE / EPB, 256, edge_smem>>>(Z, h, ei, edf, edv,
                                              be, bm1, bm2, bv1, bv2);
    node_kernel<<<(NN + NPB - 1) / NPB, 256, node_smem>>>(h, bs1, bs2, out);
}